// round 9
// baseline (speedup 1.0000x reference)
#include <cuda_runtime.h>

// Problem constants
constexpr int B  = 4;
constexpr int S  = 2048;
constexpr int D  = 1024;
constexpr int H  = 16;
constexpr int DK = 10;
constexpr int DV = 12;
constexpr int BH   = B * H;      // 64
constexpr int ROWS = B * S;      // 8192
constexpr int NCQ  = H * DK;     // 160
constexpr int NCV  = H * DV;     // 192

// Scratch (device globals; no allocation allowed)
__device__ __align__(16) float g_q [BH * S * DK];   // [bh][s][dk], pre-scaled by log2e/sqrt(dk)
__device__ __align__(16) float g_kT[BH * DK * S];   // [bh][dk][s]
__device__ __align__(16) float g_v [BH * S * DV];   // [bh][s][dv]
__device__ __align__(16) float g_hd[ROWS * NCV];    // concat heads
__device__ __align__(16) float g_wq[D * NCQ];       // Wt[d][h*DK+k]
__device__ __align__(16) float g_wk[D * NCQ];
__device__ __align__(16) float g_wv[D * NCV];

typedef unsigned long long u64;

__device__ __forceinline__ u64 pk(float lo, float hi) {
    u64 r; asm("mov.b64 %0, {%1, %2};" : "=l"(r) : "f"(lo), "f"(hi)); return r;
}
__device__ __forceinline__ void upk(u64 v, float& lo, float& hi) {
    asm("mov.b64 {%0, %1}, %2;" : "=f"(lo), "=f"(hi) : "l"(v));
}
__device__ __forceinline__ void fma2(u64& d, u64 a, u64 b) {
    asm("fma.rn.f32x2 %0, %1, %2, %0;" : "+l"(d) : "l"(a), "l"(b));
}
__device__ __forceinline__ void add2(u64& d, u64 a) {
    asm("add.rn.f32x2 %0, %0, %1;" : "+l"(d) : "l"(a));
}
__device__ __forceinline__ float ex2(float x) {
    float r; asm("ex2.approx.ftz.f32 %0, %1;" : "=f"(r) : "f"(x)); return r;
}

// ---------------------------------------------------------------------------
// Fused weight transpose: W[h][d][k] -> Wt[d][h*DKV+k] for Q, K, V weights.
// ---------------------------------------------------------------------------
__global__ void wtrans_kernel(const float* __restrict__ WQ,
                              const float* __restrict__ WK,
                              const float* __restrict__ WV) {
    int which = blockIdx.y;
    int NC  = (which == 2) ? NCV : NCQ;
    int DKV = (which == 2) ? DV : DK;
    const float* W = (which == 0) ? WQ : (which == 1) ? WK : WV;
    float* dst     = (which == 0) ? g_wq : (which == 1) ? g_wk : g_wv;
    int o = blockIdx.x * 256 + threadIdx.x;
    if (o >= D * NC) return;
    int d = o / NC, c = o % NC;
    int h = c / DKV, k = c % DKV;
    dst[o] = W[(h * D + d) * DKV + k];
}

// ---------------------------------------------------------------------------
// Projection GEMM v6 body: 128 threads, BM=64 rows, col-block NCb.
// Per-thread: 4 rows (ty+16i) x NCpt cols (col-pair packed). 3 CTAs/SM.
// ---------------------------------------------------------------------------
template<int NC, int NCb, int NCpt, int MODE>
__device__ __forceinline__ void proj_body(const float* __restrict__ X,
                                          float (*sX)[36], float (*sW)[96]) {
    constexpr int NU  = NCpt / 2;                // 5 or 6 col-pairs
    constexpr int DKV = (MODE == 2) ? DV : DK;
    constexpr int GS  = 12;                      // sW group stride (bank partition)
    constexpr int WL  = NCb / 4;                 // 20 or 24 W scalars per thread
    const float* __restrict__ Wt = (MODE == 0) ? g_wq : (MODE == 1) ? g_wk : g_wv;

    int t  = threadIdx.x;
    int tx = t & 7, ty = t >> 3;                 // ty in 0..15
    int row0 = blockIdx.x * 64;
    int cb   = blockIdx.y * NCb;

    u64 acc[4][NU];
    #pragma unroll
    for (int i = 0; i < 4; i++)
        #pragma unroll
        for (int j = 0; j < NU; j++) acc[i][j] = 0ull;

    float4 rx[4];
    float  rw[WL];

    auto ldg_tile = [&](int kt) {
        #pragma unroll
        for (int i = 0; i < 4; i++) {
            int f = t + i * 128;
            int r = f >> 3, c4 = f & 7;
            rx[i] = *(const float4*)&X[(row0 + r) * D + kt + c4 * 4];
        }
        #pragma unroll
        for (int i = 0; i < WL; i++) {
            int f = t + i * 128;
            int r = f / NCb, c = f % NCb;
            rw[i] = Wt[(kt + r) * NC + cb + c];
        }
    };

    ldg_tile(0);

    for (int kt = 0; kt < D; kt += 32) {
        __syncthreads();
        #pragma unroll
        for (int i = 0; i < 4; i++) {
            int f = t + i * 128;
            int r = f >> 3, c4 = f & 7;
            *(float4*)&sX[r][c4 * 4] = rx[i];
        }
        #pragma unroll
        for (int i = 0; i < WL; i++) {
            int f = t + i * 128;
            int r = f / NCb, c = f % NCb;
            sW[r][(c / NCpt) * GS + c % NCpt] = rw[i];
        }
        __syncthreads();

        if (kt + 32 < D) ldg_tile(kt + 32);

        #pragma unroll
        for (int kk2 = 0; kk2 < 16; kk2++) {
            int kk = 2 * kk2;
            u64 ap[4];
            #pragma unroll
            for (int i = 0; i < 4; i++) ap[i] = *(const u64*)&sX[ty + 16 * i][kk];

            u64 w0[NU], w1[NU];
            #pragma unroll
            for (int kb = 0; kb < 2; kb++) {
                u64* w = kb ? w1 : w0;
                const float* base = &sW[kk + kb][tx * GS];
                float4 p0 = *(const float4*)base;
                float4 p1 = *(const float4*)(base + 4);
                w[0] = pk(p0.x, p0.y); w[1] = pk(p0.z, p0.w);
                w[2] = pk(p1.x, p1.y); w[3] = pk(p1.z, p1.w);
                if (NCpt == 10) {
                    float2 p2 = *(const float2*)(base + 8);
                    w[4] = pk(p2.x, p2.y);
                } else {
                    float4 p2 = *(const float4*)(base + 8);
                    w[4] = pk(p2.x, p2.y); w[5] = pk(p2.z, p2.w);
                }
            }

            #pragma unroll
            for (int i = 0; i < 4; i++) {
                float a0, a1; upk(ap[i], a0, a1);
                u64 A0 = pk(a0, a0), A1 = pk(a1, a1);
                #pragma unroll
                for (int j = 0; j < NU; j++) {
                    fma2(acc[i][j], A0, w0[j]);
                    fma2(acc[i][j], A1, w1[j]);
                }
            }
        }
    }

    const float QSCALE = 1.4426950408889634f * 0.31622776601683794f; // log2(e)/sqrt(10)
    #pragma unroll
    for (int i = 0; i < 4; i++) {
        int gr = row0 + ty + 16 * i;
        int b  = gr >> 11;
        int s  = gr & (S - 1);
        #pragma unroll
        for (int j = 0; j < NU; j++) {
            float v0, v1; upk(acc[i][j], v0, v1);
            if (MODE == 0) { v0 *= QSCALE; v1 *= QSCALE; }
            #pragma unroll
            for (int ll = 0; ll < 2; ll++) {
                int c = cb + tx * NCpt + 2 * j + ll;
                int h = c / DKV, k = c % DKV;
                float v = ll ? v1 : v0;
                if (MODE == 0)      g_q [((b * H + h) * S + s) * DK + k] = v;
                else if (MODE == 1) g_kT[((b * H + h) * DK + k) * S + s] = v;
                else                g_v [((b * H + h) * S + s) * DV + k] = v;
            }
        }
    }
}

// Fused launcher: z = 0 -> Q, 1 -> K, 2 -> V. grid (128, 2, 3) = 768 CTAs.
__global__ __launch_bounds__(128, 3) void proj3_kernel(const float* __restrict__ Q,
                                                       const float* __restrict__ K,
                                                       const float* __restrict__ V) {
    __shared__ __align__(16) float sX[64][36];
    __shared__ __align__(16) float sW[32][96];
    if (blockIdx.z == 0)      proj_body<NCQ, 80, 10, 0>(Q, sX, sW);
    else if (blockIdx.z == 1) proj_body<NCQ, 80, 10, 1>(K, sX, sW);
    else                      proj_body<NCV, 96, 12, 2>(V, sX, sW);
}

// ---------------------------------------------------------------------------
// Flash attention v7: R=2 rows/thread, 256 threads, 2 CTAs/SM.
// Register-pressure fix: V processed PER KEY (one v[6] buffer reused for
// key0 then key1) and jp unroll 1 -> peak live regs ~120 < the 128 cap from
// 2 CTAs/SM, so no serialization/spill; 4 warps/SMSP hide LDS latency.
// No-max softmax (scores small; exp2 cannot overflow fp32).
// ---------------------------------------------------------------------------
__global__ __launch_bounds__(256, 2) void flash_kernel() {
    int bh = blockIdx.y;
    int t  = threadIdx.x;
    int r0 = blockIdx.x * 512 + t * 2;

    const float* qp = g_q + (bh * S + r0) * DK;
    u64 qb[2][DK];
    #pragma unroll
    for (int r = 0; r < 2; r++)
        #pragma unroll
        for (int d = 0; d < DK; d++) {
            float v = qp[r * DK + d];
            qb[r][d] = pk(v, v);
        }

    u64 acc[2][6];
    #pragma unroll
    for (int r = 0; r < 2; r++)
        #pragma unroll
        for (int j = 0; j < 6; j++) acc[r][j] = 0ull;
    u64 l2[2] = {0ull, 0ull};

    __shared__ __align__(16) float sK[64 * 20];    // [jp][d][2 keys] pair-major
    __shared__ __align__(16) float sV[128 * DV];

    float rk[5], rv[6];
    auto ldg_tile = [&](int j0) {
        #pragma unroll
        for (int i = 0; i < 5; i++) {
            int idx = i * 256 + t;
            int d = idx >> 7, j = idx & 127;
            rk[i] = g_kT[(bh * DK + d) * S + j0 + j];
        }
        #pragma unroll
        for (int i = 0; i < 6; i++)
            rv[i] = g_v[(bh * S + j0) * DV + i * 256 + t];
    };

    ldg_tile(0);

    for (int j0 = 0; j0 < S; j0 += 128) {
        __syncthreads();
        #pragma unroll
        for (int i = 0; i < 5; i++) {
            int idx = i * 256 + t;
            int d = idx >> 7, j = idx & 127;
            sK[(j >> 1) * 20 + d * 2 + (j & 1)] = rk[i];
        }
        #pragma unroll
        for (int i = 0; i < 6; i++)
            sV[i * 256 + t] = rv[i];
        __syncthreads();

        if (j0 + 128 < S) ldg_tile(j0 + 128);

        #pragma unroll 1
        for (int jp = 0; jp < 64; jp++) {
            // K pair for all 10 dims: 5 LDS.128
            const ulonglong2* kp = (const ulonglong2*)&sK[jp * 20];
            u64 k2[DK];
            #pragma unroll
            for (int i = 0; i < 5; i++) {
                ulonglong2 kk = kp[i];
                k2[2 * i] = kk.x; k2[2 * i + 1] = kk.y;
            }

            u64 s[2] = {0ull, 0ull};
            #pragma unroll
            for (int d = 0; d < DK; d++) {
                #pragma unroll
                for (int r = 0; r < 2; r++) fma2(s[r], qb[r][d], k2[d]);
            }

            u64 P0[2], P1[2];
            #pragma unroll
            for (int r = 0; r < 2; r++) {
                float s0, s1; upk(s[r], s0, s1);
                float p0 = ex2(s0), p1 = ex2(s1);
                add2(l2[r], pk(p0, p1));
                P0[r] = pk(p0, p0); P1[r] = pk(p1, p1);
            }

            // key 0 of the pair: v[6] reused buffer (3 LDS.128)
            {
                const ulonglong2* vp = (const ulonglong2*)&sV[(jp * 2) * DV];
                u64 v[6];
                #pragma unroll
                for (int i = 0; i < 3; i++) {
                    ulonglong2 a = vp[i];
                    v[2 * i] = a.x; v[2 * i + 1] = a.y;
                }
                #pragma unroll
                for (int r = 0; r < 2; r++)
                    #pragma unroll
                    for (int j = 0; j < 6; j++) fma2(acc[r][j], P0[r], v[j]);
            }
            // key 1 of the pair
            {
                const ulonglong2* vp = (const ulonglong2*)&sV[(jp * 2 + 1) * DV];
                u64 v[6];
                #pragma unroll
                for (int i = 0; i < 3; i++) {
                    ulonglong2 a = vp[i];
                    v[2 * i] = a.x; v[2 * i + 1] = a.y;
                }
                #pragma unroll
                for (int r = 0; r < 2; r++)
                    #pragma unroll
                    for (int j = 0; j < 6; j++) fma2(acc[r][j], P1[r], v[j]);
            }
        }
    }

    int b = bh >> 4, h = bh & 15;
    #pragma unroll
    for (int r = 0; r < 2; r++) {
        float la, lb; upk(l2[r], la, lb);
        float inv = 1.f / (la + lb);
        float* op = g_hd + (b * S + r0 + r) * NCV + h * DV;
        #pragma unroll
        for (int j = 0; j < 6; j++) {
            float x0, x1; upk(acc[r][j], x0, x1);
            op[2 * j]     = x0 * inv;
            op[2 * j + 1] = x1 * inv;
        }
    }
}

// ---------------------------------------------------------------------------
// Output projection v3: out = g_hd[8192][192] @ WO[192][1024].
// Block 256 thr, 32 rows, 512-col half. kk-loop unroll 8.
// ---------------------------------------------------------------------------
__global__ __launch_bounds__(256, 2) void oproj_kernel(const float* __restrict__ WO,
                                                       float* __restrict__ out) {
    __shared__ __align__(16) float sHt[NCV][34];
    int t = threadIdx.x;
    int row0 = blockIdx.x * 32;
    int c0   = blockIdx.y * 512 + t * 2;

    #pragma unroll
    for (int i = 0; i < 24; i++) {
        int idx = i * 256 + t;
        int r = idx / NCV, k = idx % NCV;
        sHt[k][r] = g_hd[(row0 + r) * NCV + k];
    }
    __syncthreads();

    u64 acc[16][2];
    #pragma unroll
    for (int rp = 0; rp < 16; rp++) { acc[rp][0] = 0ull; acc[rp][1] = 0ull; }

    #pragma unroll 8
    for (int kk = 0; kk < NCV; kk++) {
        float2 w = *(const float2*)&WO[kk * D + c0];
        u64 w0 = pk(w.x, w.x), w1 = pk(w.y, w.y);
        #pragma unroll
        for (int rp = 0; rp < 16; rp++) {
            u64 h2 = *(const u64*)&sHt[kk][2 * rp];
            fma2(acc[rp][0], h2, w0);
            fma2(acc[rp][1], h2, w1);
        }
    }

    #pragma unroll
    for (int rp = 0; rp < 16; rp++) {
        float a0, a1, b0, b1;
        upk(acc[rp][0], a0, a1);
        upk(acc[rp][1], b0, b1);
        *(float2*)&out[(row0 + 2 * rp) * D + c0]     = make_float2(a0, b0);
        *(float2*)&out[(row0 + 2 * rp + 1) * D + c0] = make_float2(a1, b1);
    }
}

// ---------------------------------------------------------------------------
extern "C" void kernel_launch(void* const* d_in, const int* in_sizes, int n_in,
                              void* d_out, int out_size) {
    (void)in_sizes; (void)n_in; (void)out_size;
    const float* Q  = (const float*)d_in[0];
    const float* K  = (const float*)d_in[1];
    const float* V  = (const float*)d_in[2];
    const float* WQ = (const float*)d_in[3];
    const float* WK = (const float*)d_in[4];
    const float* WV = (const float*)d_in[5];
    const float* WO = (const float*)d_in[6];
    float* out = (float*)d_out;

    wtrans_kernel<<<dim3((D * NCV + 255) / 256, 3), 256>>>(WQ, WK, WV);

    proj3_kernel<<<dim3(ROWS / 64, 2, 3), 128>>>(Q, K, V);

    flash_kernel<<<dim3(S / 512, BH), 256>>>();

    oproj_kernel<<<dim3(ROWS / 32, 2), 256>>>(WO, out);
}

// round 10
// speedup vs baseline: 1.0244x; 1.0244x over previous
#include <cuda_runtime.h>

// Problem constants
constexpr int B  = 4;
constexpr int S  = 2048;
constexpr int D  = 1024;
constexpr int H  = 16;
constexpr int DK = 10;
constexpr int DV = 12;
constexpr int BH   = B * H;      // 64
constexpr int ROWS = B * S;      // 8192
constexpr int NCQ  = H * DK;     // 160
constexpr int NCV  = H * DV;     // 192

// Scratch (device globals; no allocation allowed)
__device__ __align__(16) float g_q [BH * S * DK];   // [bh][s][dk], pre-scaled by log2e/sqrt(dk)
__device__ __align__(16) float g_kT[BH * DK * S];   // [bh][dk][s]
__device__ __align__(16) float g_v [BH * S * DV];   // [bh][s][dv]
__device__ __align__(16) float g_hd[ROWS * NCV];    // concat heads
__device__ __align__(16) float g_wq[D * NCQ];       // Wt[d][h*DK+k]
__device__ __align__(16) float g_wk[D * NCQ];
__device__ __align__(16) float g_wv[D * NCV];

typedef unsigned long long u64;

__device__ __forceinline__ u64 pk(float lo, float hi) {
    u64 r; asm("mov.b64 %0, {%1, %2};" : "=l"(r) : "f"(lo), "f"(hi)); return r;
}
__device__ __forceinline__ void upk(u64 v, float& lo, float& hi) {
    asm("mov.b64 {%0, %1}, %2;" : "=f"(lo), "=f"(hi) : "l"(v));
}
__device__ __forceinline__ void fma2(u64& d, u64 a, u64 b) {
    asm("fma.rn.f32x2 %0, %1, %2, %0;" : "+l"(d) : "l"(a), "l"(b));
}
__device__ __forceinline__ void add2(u64& d, u64 a) {
    asm("add.rn.f32x2 %0, %0, %1;" : "+l"(d) : "l"(a));
}
__device__ __forceinline__ float ex2(float x) {
    float r; asm("ex2.approx.ftz.f32 %0, %1;" : "=f"(r) : "f"(x)); return r;
}

// ---------------------------------------------------------------------------
// Fused weight transpose: W[h][d][k] -> Wt[d][h*DKV+k] for Q, K, V weights.
// ---------------------------------------------------------------------------
__global__ void wtrans_kernel(const float* __restrict__ WQ,
                              const float* __restrict__ WK,
                              const float* __restrict__ WV) {
    int which = blockIdx.y;
    int NC  = (which == 2) ? NCV : NCQ;
    int DKV = (which == 2) ? DV : DK;
    const float* W = (which == 0) ? WQ : (which == 1) ? WK : WV;
    float* dst     = (which == 0) ? g_wq : (which == 1) ? g_wk : g_wv;
    int o = blockIdx.x * 256 + threadIdx.x;
    if (o >= D * NC) return;
    int d = o / NC, c = o % NC;
    int h = c / DKV, k = c % DKV;
    dst[o] = W[(h * D + d) * DKV + k];
}

// ---------------------------------------------------------------------------
// Projection GEMM v6 body: 128 threads, BM=64 rows, col-block NCb.
// Per-thread: 4 rows (ty+16i) x NCpt cols (col-pair packed). 3 CTAs/SM.
// ---------------------------------------------------------------------------
template<int NC, int NCb, int NCpt, int MODE>
__device__ __forceinline__ void proj_body(const float* __restrict__ X,
                                          float (*sX)[36], float (*sW)[96]) {
    constexpr int NU  = NCpt / 2;                // 5 or 6 col-pairs
    constexpr int DKV = (MODE == 2) ? DV : DK;
    constexpr int GS  = 12;                      // sW group stride (bank partition)
    constexpr int WL  = NCb / 4;                 // 20 or 24 W scalars per thread
    const float* __restrict__ Wt = (MODE == 0) ? g_wq : (MODE == 1) ? g_wk : g_wv;

    int t  = threadIdx.x;
    int tx = t & 7, ty = t >> 3;                 // ty in 0..15
    int row0 = blockIdx.x * 64;
    int cb   = blockIdx.y * NCb;

    u64 acc[4][NU];
    #pragma unroll
    for (int i = 0; i < 4; i++)
        #pragma unroll
        for (int j = 0; j < NU; j++) acc[i][j] = 0ull;

    float4 rx[4];
    float  rw[WL];

    auto ldg_tile = [&](int kt) {
        #pragma unroll
        for (int i = 0; i < 4; i++) {
            int f = t + i * 128;
            int r = f >> 3, c4 = f & 7;
            rx[i] = *(const float4*)&X[(row0 + r) * D + kt + c4 * 4];
        }
        #pragma unroll
        for (int i = 0; i < WL; i++) {
            int f = t + i * 128;
            int r = f / NCb, c = f % NCb;
            rw[i] = Wt[(kt + r) * NC + cb + c];
        }
    };

    ldg_tile(0);

    for (int kt = 0; kt < D; kt += 32) {
        __syncthreads();
        #pragma unroll
        for (int i = 0; i < 4; i++) {
            int f = t + i * 128;
            int r = f >> 3, c4 = f & 7;
            *(float4*)&sX[r][c4 * 4] = rx[i];
        }
        #pragma unroll
        for (int i = 0; i < WL; i++) {
            int f = t + i * 128;
            int r = f / NCb, c = f % NCb;
            sW[r][(c / NCpt) * GS + c % NCpt] = rw[i];
        }
        __syncthreads();

        if (kt + 32 < D) ldg_tile(kt + 32);

        #pragma unroll
        for (int kk2 = 0; kk2 < 16; kk2++) {
            int kk = 2 * kk2;
            u64 ap[4];
            #pragma unroll
            for (int i = 0; i < 4; i++) ap[i] = *(const u64*)&sX[ty + 16 * i][kk];

            u64 w0[NU], w1[NU];
            #pragma unroll
            for (int kb = 0; kb < 2; kb++) {
                u64* w = kb ? w1 : w0;
                const float* base = &sW[kk + kb][tx * GS];
                float4 p0 = *(const float4*)base;
                float4 p1 = *(const float4*)(base + 4);
                w[0] = pk(p0.x, p0.y); w[1] = pk(p0.z, p0.w);
                w[2] = pk(p1.x, p1.y); w[3] = pk(p1.z, p1.w);
                if (NCpt == 10) {
                    float2 p2 = *(const float2*)(base + 8);
                    w[4] = pk(p2.x, p2.y);
                } else {
                    float4 p2 = *(const float4*)(base + 8);
                    w[4] = pk(p2.x, p2.y); w[5] = pk(p2.z, p2.w);
                }
            }

            #pragma unroll
            for (int i = 0; i < 4; i++) {
                float a0, a1; upk(ap[i], a0, a1);
                u64 A0 = pk(a0, a0), A1 = pk(a1, a1);
                #pragma unroll
                for (int j = 0; j < NU; j++) {
                    fma2(acc[i][j], A0, w0[j]);
                    fma2(acc[i][j], A1, w1[j]);
                }
            }
        }
    }

    const float QSCALE = 1.4426950408889634f * 0.31622776601683794f; // log2(e)/sqrt(10)
    #pragma unroll
    for (int i = 0; i < 4; i++) {
        int gr = row0 + ty + 16 * i;
        int b  = gr >> 11;
        int s  = gr & (S - 1);
        #pragma unroll
        for (int j = 0; j < NU; j++) {
            float v0, v1; upk(acc[i][j], v0, v1);
            if (MODE == 0) { v0 *= QSCALE; v1 *= QSCALE; }
            #pragma unroll
            for (int ll = 0; ll < 2; ll++) {
                int c = cb + tx * NCpt + 2 * j + ll;
                int h = c / DKV, k = c % DKV;
                float v = ll ? v1 : v0;
                if (MODE == 0)      g_q [((b * H + h) * S + s) * DK + k] = v;
                else if (MODE == 1) g_kT[((b * H + h) * DK + k) * S + s] = v;
                else                g_v [((b * H + h) * S + s) * DV + k] = v;
            }
        }
    }
}

// Fused launcher: z = 0 -> Q, 1 -> K, 2 -> V. grid (128, 2, 3) = 768 CTAs.
__global__ __launch_bounds__(128, 3) void proj3_kernel(const float* __restrict__ Q,
                                                       const float* __restrict__ K,
                                                       const float* __restrict__ V) {
    __shared__ __align__(16) float sX[64][36];
    __shared__ __align__(16) float sW[32][96];
    if (blockIdx.z == 0)      proj_body<NCQ, 80, 10, 0>(Q, sX, sW);
    else if (blockIdx.z == 1) proj_body<NCQ, 80, 10, 1>(K, sX, sW);
    else                      proj_body<NCV, 96, 12, 2>(V, sX, sW);
}

// ---------------------------------------------------------------------------
// Flash attention (R8 version, reverted): R=2 rows/thread, 256 threads,
// 2 CTAs/SM; jp unroll 4; dual v0/v1 buffers.
// Uniform (broadcast) sK/sV addresses per jp; register-prefetch of next tile.
// No-max softmax (scores small; exp2 cannot overflow fp32).
// ---------------------------------------------------------------------------
__global__ __launch_bounds__(256, 2) void flash_kernel() {
    int bh = blockIdx.y;
    int t  = threadIdx.x;
    int r0 = blockIdx.x * 512 + t * 2;

    const float* qp = g_q + (bh * S + r0) * DK;
    u64 qb[2][DK];
    #pragma unroll
    for (int r = 0; r < 2; r++)
        #pragma unroll
        for (int d = 0; d < DK; d++) {
            float v = qp[r * DK + d];
            qb[r][d] = pk(v, v);
        }

    u64 acc[2][6];
    #pragma unroll
    for (int r = 0; r < 2; r++)
        #pragma unroll
        for (int j = 0; j < 6; j++) acc[r][j] = 0ull;
    u64 l2[2] = {0ull, 0ull};

    __shared__ __align__(16) float sK[64 * 20];    // [jp][d][2 keys] pair-major
    __shared__ __align__(16) float sV[128 * DV];

    float rk[5], rv[6];
    auto ldg_tile = [&](int j0) {
        #pragma unroll
        for (int i = 0; i < 5; i++) {
            int idx = i * 256 + t;
            int d = idx >> 7, j = idx & 127;
            rk[i] = g_kT[(bh * DK + d) * S + j0 + j];
        }
        #pragma unroll
        for (int i = 0; i < 6; i++)
            rv[i] = g_v[(bh * S + j0) * DV + i * 256 + t];
    };

    ldg_tile(0);

    for (int j0 = 0; j0 < S; j0 += 128) {
        __syncthreads();
        #pragma unroll
        for (int i = 0; i < 5; i++) {
            int idx = i * 256 + t;
            int d = idx >> 7, j = idx & 127;
            sK[(j >> 1) * 20 + d * 2 + (j & 1)] = rk[i];
        }
        #pragma unroll
        for (int i = 0; i < 6; i++)
            sV[i * 256 + t] = rv[i];
        __syncthreads();

        if (j0 + 128 < S) ldg_tile(j0 + 128);

        #pragma unroll 4
        for (int jp = 0; jp < 64; jp++) {
            const ulonglong2* kp = (const ulonglong2*)&sK[jp * 20];
            u64 k2[DK];
            #pragma unroll
            for (int i = 0; i < 5; i++) {
                ulonglong2 kk = kp[i];
                k2[2 * i] = kk.x; k2[2 * i + 1] = kk.y;
            }

            u64 s[2] = {0ull, 0ull};
            #pragma unroll
            for (int d = 0; d < DK; d++) {
                #pragma unroll
                for (int r = 0; r < 2; r++) fma2(s[r], qb[r][d], k2[d]);
            }

            u64 P0[2], P1[2];
            #pragma unroll
            for (int r = 0; r < 2; r++) {
                float s0, s1; upk(s[r], s0, s1);
                float p0 = ex2(s0), p1 = ex2(s1);
                add2(l2[r], pk(p0, p1));
                P0[r] = pk(p0, p0); P1[r] = pk(p1, p1);
            }

            const ulonglong2* vp = (const ulonglong2*)&sV[jp * 2 * DV];
            u64 v0[6], v1[6];
            #pragma unroll
            for (int i = 0; i < 3; i++) {
                ulonglong2 a = vp[i], bq = vp[3 + i];
                v0[2 * i] = a.x;  v0[2 * i + 1] = a.y;
                v1[2 * i] = bq.x; v1[2 * i + 1] = bq.y;
            }
            #pragma unroll
            for (int r = 0; r < 2; r++)
                #pragma unroll
                for (int j = 0; j < 6; j++) {
                    fma2(acc[r][j], P0[r], v0[j]);
                    fma2(acc[r][j], P1[r], v1[j]);
                }
        }
    }

    int b = bh >> 4, h = bh & 15;
    #pragma unroll
    for (int r = 0; r < 2; r++) {
        float la, lb; upk(l2[r], la, lb);
        float inv = 1.f / (la + lb);
        float* op = g_hd + (b * S + r0 + r) * NCV + h * DV;
        #pragma unroll
        for (int j = 0; j < 6; j++) {
            float x0, x1; upk(acc[r][j], x0, x1);
            op[2 * j]     = x0 * inv;
            op[2 * j + 1] = x1 * inv;
        }
    }
}

// ---------------------------------------------------------------------------
// Output projection v4: out = g_hd[8192][192] @ WO[192][1024].
// Block 256 thr, 32 rows, 512-col half, kk unroll 8. sHt rows padded to 36
// floats (16B-aligned) so row-QUAD loads are single broadcast LDS.128:
// 8 LDS.128 per kk instead of 16 LDS.64 -> fma issue fraction ~70%.
// ---------------------------------------------------------------------------
__global__ __launch_bounds__(256, 2) void oproj_kernel(const float* __restrict__ WO,
                                                       float* __restrict__ out) {
    __shared__ __align__(16) float sHt[NCV][36];
    int t = threadIdx.x;
    int row0 = blockIdx.x * 32;
    int c0   = blockIdx.y * 512 + t * 2;

    #pragma unroll
    for (int i = 0; i < 24; i++) {
        int idx = i * 256 + t;
        int r = idx / NCV, k = idx % NCV;
        sHt[k][r] = g_hd[(row0 + r) * NCV + k];
    }
    __syncthreads();

    u64 acc[16][2];
    #pragma unroll
    for (int rp = 0; rp < 16; rp++) { acc[rp][0] = 0ull; acc[rp][1] = 0ull; }

    #pragma unroll 8
    for (int kk = 0; kk < NCV; kk++) {
        float2 w = *(const float2*)&WO[kk * D + c0];
        u64 w0 = pk(w.x, w.x), w1 = pk(w.y, w.y);
        #pragma unroll
        for (int q = 0; q < 8; q++) {
            ulonglong2 hh = *(const ulonglong2*)&sHt[kk][4 * q];  // rows 4q..4q+3
            fma2(acc[2 * q][0],     hh.x, w0);
            fma2(acc[2 * q][1],     hh.x, w1);
            fma2(acc[2 * q + 1][0], hh.y, w0);
            fma2(acc[2 * q + 1][1], hh.y, w1);
        }
    }

    #pragma unroll
    for (int rp = 0; rp < 16; rp++) {
        float a0, a1, b0, b1;
        upk(acc[rp][0], a0, a1);
        upk(acc[rp][1], b0, b1);
        *(float2*)&out[(row0 + 2 * rp) * D + c0]     = make_float2(a0, b0);
        *(float2*)&out[(row0 + 2 * rp + 1) * D + c0] = make_float2(a1, b1);
    }
}

// ---------------------------------------------------------------------------
extern "C" void kernel_launch(void* const* d_in, const int* in_sizes, int n_in,
                              void* d_out, int out_size) {
    (void)in_sizes; (void)n_in; (void)out_size;
    const float* Q  = (const float*)d_in[0];
    const float* K  = (const float*)d_in[1];
    const float* V  = (const float*)d_in[2];
    const float* WQ = (const float*)d_in[3];
    const float* WK = (const float*)d_in[4];
    const float* WV = (const float*)d_in[5];
    const float* WO = (const float*)d_in[6];
    float* out = (float*)d_out;

    wtrans_kernel<<<dim3((D * NCV + 255) / 256, 3), 256>>>(WQ, WK, WV);

    proj3_kernel<<<dim3(ROWS / 64, 2, 3), 128>>>(Q, K, V);

    flash_kernel<<<dim3(S / 512, BH), 256>>>();

    oproj_kernel<<<dim3(ROWS / 32, 2), 256>>>(WO, out);
}